// round 4
// baseline (speedup 1.0000x reference)
#include <cuda_runtime.h>

#define NT 256
#define BT 8

typedef unsigned long long u64;

// ---------------- packed f32x2 helpers ----------------
__device__ __forceinline__ void ffma2(u64 &acc, u64 a, u64 w) {
    asm("fma.rn.f32x2 %0, %1, %2, %0;" : "+l"(acc) : "l"(a), "l"(w));
}
__device__ __forceinline__ float sum2(u64 v) {
    return __uint_as_float((unsigned int)v) + __uint_as_float((unsigned int)(v >> 32));
}

// ---------------- activations ----------------
__device__ __forceinline__ float softplus_f(float x) {
    float r = __logf(1.f + __expf(x));
    return (x > 15.f) ? x : r;
}
__device__ __forceinline__ float tanh_f(float x) {
    float xx = fminf(fmaxf(x, -12.f), 12.f);
    float e = __expf(2.f * xx);
    return (e - 1.f) * __fdividef(1.f, e + 1.f);
}

// ---------------- vw3 in k-major quad-interleaved layout ----------------
// g_vw3q[(k>>2)*2048 + c*4 + (k&3)] = vw3[c*128 + k],  c in [0,512), k in [0,128)
__device__ float g_vw3q[512 * 128];

__global__ void prep_vw3(const float* __restrict__ vw3) {
    int id = blockIdx.x * blockDim.x + threadIdx.x;   // 65536
    int c = id >> 7;
    int k = id & 127;
    g_vw3q[(k >> 2) * 2048 + (c << 2) + (k & 3)] = vw3[id];
}

// ---------------- smem layout (floats) ----------------
#define OFF_W1 0          // 128 x 68
#define OFF_W2 8704       // 128 x 132
#define OFF_B1 25600      // 128
#define OFF_B2 25728      // 128
#define OFF_B3 25856      // 512
#define OFF_LW 26368      // 64
#define OFF_Y  26432      // 8 x 64
#define OFF_YT 26944      // 8 x 64
#define OFF_H1 27456      // 8 x 128
#define OFF_H2 28480      // 8 x 128
#define OFF_K  29504      // 6 x 512
#define OFF_DX 32576      // 8 x 8
#define SMEM_FLOATS 32640
#define SMEM_BYTES (SMEM_FLOATS * 4)

enum { ACT_ID = 0, ACT_RELU = 1, ACT_SP = 2 };

// OUT[8][C] = act( ACTS[8][K] @ W[C][K]^T + bias ),  W padded to stride WS in smem.
// Weight LDS for iteration kq+4 issued one iteration early (covers 29cyc LDS lat).
template<int C, int K, int WS, int ACT>
__device__ __forceinline__ void dense(const float* __restrict__ wp,
                                      const float* __restrict__ bias,
                                      const float* __restrict__ actbuf,
                                      float* __restrict__ outp, int tid) {
    constexpr int RPT = (8 * C) / NT;            // 4 for C=128, 2 for C=64
    const int c  = tid % C;
    const int r0 = (tid / C) * RPT;
    u64 acc[RPT][2];
#pragma unroll
    for (int i = 0; i < RPT; i++) { acc[i][0] = 0ull; acc[i][1] = 0ull; }
    const float* wr = wp + c * WS;
    ulonglong2 w = *(const ulonglong2*)(wr);
#pragma unroll
    for (int k = 0; k < K; k += 4) {
        ulonglong2 wn;
        if (k + 4 < K) wn = *(const ulonglong2*)(wr + k + 4);
#pragma unroll
        for (int i = 0; i < RPT; i++) {
            ulonglong2 a = *(const ulonglong2*)(actbuf + (r0 + i) * K + k);
            ffma2(acc[i][0], a.x, w.x);
            ffma2(acc[i][1], a.y, w.y);
        }
        if (k + 4 < K) w = wn;
    }
    float b = bias[c];
#pragma unroll
    for (int i = 0; i < RPT; i++) {
        float v = sum2(acc[i][0]) + sum2(acc[i][1]) + b;
        if (ACT == ACT_RELU) v = fmaxf(v, 0.f);
        if (ACT == ACT_SP)   v = softplus_f(v);
        outp[(r0 + i) * C + c] = v;
    }
}

// L3 (512 outs, K=128) + tanh + einsum with dx -> kout[8][64]
// thread owns columns c0=tid and c1=tid+256 for all 8 rows.
// Depth-4 explicit register pipeline on the vw3 LDG stream: ~4 iterations
// (>350 cyc) of cover for the 234-262 cyc L2 latency, 8 loads in flight.
__device__ __forceinline__ void l3contract(const float* __restrict__ h2s,
                                           const float* __restrict__ b3s,
                                           const float* __restrict__ dxs,
                                           float* __restrict__ kout, int tid) {
    u64 acc0[8], acc1[8];
#pragma unroll
    for (int r = 0; r < 8; r++) { acc0[r] = 0ull; acc1[r] = 0ull; }

    const float* gb = g_vw3q + tid * 4;
    ulonglong2 p0[4], p1[4];
#pragma unroll
    for (int i = 0; i < 4; i++) {
        p0[i] = *(const ulonglong2*)(gb + i * 2048);
        p1[i] = *(const ulonglong2*)(gb + i * 2048 + 1024);
    }

#pragma unroll
    for (int kq = 0; kq < 32; kq++) {
        ulonglong2 w0 = p0[kq & 3];
        ulonglong2 w1 = p1[kq & 3];
        if (kq + 4 < 32) {
            p0[kq & 3] = *(const ulonglong2*)(gb + (kq + 4) * 2048);
            p1[kq & 3] = *(const ulonglong2*)(gb + (kq + 4) * 2048 + 1024);
        }
#pragma unroll
        for (int r = 0; r < 8; r++) {
            ulonglong2 a = *(const ulonglong2*)(h2s + r * 128 + kq * 4);
            ffma2(acc0[r], a.x, w0.x);
            ffma2(acc0[r], a.y, w0.y);
            ffma2(acc1[r], a.x, w1.x);
            ffma2(acc1[r], a.y, w1.y);
        }
    }

    const int h0 = tid >> 3;            // 0..31
    const int d  = tid & 7;
    const float b0 = b3s[tid];
    const float b1 = b3s[tid + 256];
#pragma unroll
    for (int r = 0; r < 8; r++) {
        float f0 = tanh_f(sum2(acc0[r]) + b0);
        float f1 = tanh_f(sum2(acc1[r]) + b1);
        float dxv = dxs[r * 8 + d];
        float pa = f0 * dxv;
        float pb = f1 * dxv;
        pa += __shfl_xor_sync(0xffffffffu, pa, 1);
        pa += __shfl_xor_sync(0xffffffffu, pa, 2);
        pa += __shfl_xor_sync(0xffffffffu, pa, 4);
        pb += __shfl_xor_sync(0xffffffffu, pb, 1);
        pb += __shfl_xor_sync(0xffffffffu, pb, 2);
        pb += __shfl_xor_sync(0xffffffffu, pb, 4);
        if (d == 0) {
            kout[r * 64 + h0]      = pa;
            kout[r * 64 + h0 + 32] = pb;
        }
    }
}

__device__ __forceinline__ void vf(const float* __restrict__ ysrc, float* __restrict__ kout,
                                   const float* w1p, const float* b1s,
                                   const float* w2p, const float* b2s,
                                   const float* b3s, const float* dxs,
                                   float* h1, float* h2, int tid) {
    dense<128, 64, 68, ACT_SP>(w1p, b1s, ysrc, h1, tid);
    __syncthreads();
    dense<128, 128, 132, ACT_SP>(w2p, b2s, h1, h2, tid);
    __syncthreads();
    l3contract(h2, b3s, dxs, kout, tid);
    __syncthreads();
}

__device__ __forceinline__ void write_out(const float* __restrict__ y,
                                          const float* __restrict__ lws, float lbv,
                                          float* __restrict__ out, int b0, int t, int tid) {
    int w = tid >> 5, l = tid & 31;           // warp w handles batch row w
    float p = y[w * 64 + l] * lws[l] + y[w * 64 + 32 + l] * lws[32 + l];
#pragma unroll
    for (int s = 16; s > 0; s >>= 1) p += __shfl_xor_sync(0xffffffffu, p, s);
    if (l == 0) {
        float z = p + lbv;
        out[(b0 + w) * 64 + t] = __fdividef(1.f, 1.f + __expf(-z));
    }
}

__global__ void __launch_bounds__(NT, 1)
cde_kernel(const float* __restrict__ ts, const float* __restrict__ xs,
           const float* __restrict__ iw1, const float* __restrict__ ib1,
           const float* __restrict__ iw2, const float* __restrict__ ib2,
           const float* __restrict__ iw3, const float* __restrict__ ib3,
           const float* __restrict__ vw1, const float* __restrict__ vb1,
           const float* __restrict__ vw2, const float* __restrict__ vb2,
           const float* __restrict__ vb3,
           const float* __restrict__ lw, const float* __restrict__ lb,
           float* __restrict__ out) {
    extern __shared__ float sm[];
    const int tid = threadIdx.x;
    const int b0 = blockIdx.x * BT;

    float* w1p = sm + OFF_W1;
    float* w2p = sm + OFF_W2;
    float* b1s = sm + OFF_B1;
    float* b2s = sm + OFF_B2;
    float* b3s = sm + OFF_B3;
    float* lws = sm + OFF_LW;
    float* ybuf = sm + OFF_Y;
    float* yts = sm + OFF_YT;
    float* h1 = sm + OFF_H1;
    float* h2 = sm + OFF_H2;
    float* ksb = sm + OFF_K;
    float* dxs = sm + OFF_DX;

    // ---------- initial MLP: y0 = relu-MLP(xs[:,0]) ----------
    for (int i = tid; i < 128 * 8; i += NT)   w1p[(i >> 3) * 68 + (i & 7)] = iw1[i];
    for (int i = tid; i < 128 * 128; i += NT) w2p[(i >> 7) * 132 + (i & 127)] = iw2[i];
    for (int i = tid; i < 128; i += NT) { b1s[i] = ib1[i]; b2s[i] = ib2[i]; }
    if (tid < 64) lws[tid] = lw[tid];
    if (tid < 64) {
        int r = tid >> 3, d = tid & 7;
        dxs[tid] = xs[(b0 + r) * 512 + d];          // X(t0) staged in dxs buffer
    }
    __syncthreads();
    dense<128, 8, 68, ACT_RELU>(w1p, b1s, dxs, h1, tid);
    __syncthreads();
    dense<128, 128, 132, ACT_RELU>(w2p, b2s, h1, h2, tid);
    __syncthreads();
    for (int i = tid; i < 64 * 128; i += NT)  w2p[(i >> 7) * 132 + (i & 127)] = iw3[i];
    __syncthreads();
    dense<64, 128, 132, ACT_ID>(w2p, ib3, h2, ybuf, tid);
    __syncthreads();

    // ---------- load vector-field weights ----------
    for (int i = tid; i < 128 * 64; i += NT)  w1p[(i >> 6) * 68 + (i & 63)] = vw1[i];
    for (int i = tid; i < 128 * 128; i += NT) w2p[(i >> 7) * 132 + (i & 127)] = vw2[i];
    for (int i = tid; i < 128; i += NT) { b1s[i] = vb1[i]; b2s[i] = vb2[i]; }
    for (int i = tid; i < 512; i += NT) b3s[i] = vb3[i];
    const float lbv = lb[0];
    __syncthreads();

    write_out(ybuf, lws, lbv, out, b0, 0, tid);
    __syncthreads();

    // Tsit5 coefficients
    const float A21 = 0.161f;
    const float A31 = -0.008480655492356989f, A32 = 0.335480655492357f;
    const float A41 = 2.8971530571054935f, A42 = -6.359448489975075f, A43 = 4.3622954328695815f;
    const float A51 = 5.325864828439257f, A52 = -11.748883564062828f, A53 = 7.4955393428898365f, A54 = -0.09249506636175525f;
    const float A61 = 5.86145544294642f, A62 = -12.92096931784711f, A63 = 8.159367898576159f, A64 = -0.071584973281401f, A65 = -0.028269050394068383f;
    const float B1 = 0.09646076681806523f, B2 = 0.01f, B3 = 0.4798896504144996f;
    const float B4 = 1.379008574103742f, B5 = -3.290069515436081f, B6 = 2.324710524099774f;

    float* k1 = ksb;
    float* k2 = ksb + 512;
    float* k3 = ksb + 1024;
    float* k4 = ksb + 1536;
    float* k5 = ksb + 2048;
    float* k6 = ksb + 2560;

    for (int t = 0; t < 63; t++) {
        const float dt = ts[t + 1] - ts[t];
        if (tid < 64) {
            int r = tid >> 3, d = tid & 7;
            int ix = (b0 + r) * 512 + t * 8 + d;
            dxs[tid] = (xs[ix + 8] - xs[ix]) / dt;
        }
        __syncthreads();

        // stage 1
        vf(ybuf, k1, w1p, b1s, w2p, b2s, b3s, dxs, h1, h2, tid);
        // stage 2
#pragma unroll
        for (int e = tid; e < 512; e += NT)
            yts[e] = ybuf[e] + dt * (A21 * k1[e]);
        __syncthreads();
        vf(yts, k2, w1p, b1s, w2p, b2s, b3s, dxs, h1, h2, tid);
        // stage 3
#pragma unroll
        for (int e = tid; e < 512; e += NT)
            yts[e] = ybuf[e] + dt * (A31 * k1[e] + A32 * k2[e]);
        __syncthreads();
        vf(yts, k3, w1p, b1s, w2p, b2s, b3s, dxs, h1, h2, tid);
        // stage 4
#pragma unroll
        for (int e = tid; e < 512; e += NT)
            yts[e] = ybuf[e] + dt * (A41 * k1[e] + A42 * k2[e] + A43 * k3[e]);
        __syncthreads();
        vf(yts, k4, w1p, b1s, w2p, b2s, b3s, dxs, h1, h2, tid);
        // stage 5
#pragma unroll
        for (int e = tid; e < 512; e += NT)
            yts[e] = ybuf[e] + dt * (A51 * k1[e] + A52 * k2[e] + A53 * k3[e] + A54 * k4[e]);
        __syncthreads();
        vf(yts, k5, w1p, b1s, w2p, b2s, b3s, dxs, h1, h2, tid);
        // stage 6
#pragma unroll
        for (int e = tid; e < 512; e += NT)
            yts[e] = ybuf[e] + dt * (A61 * k1[e] + A62 * k2[e] + A63 * k3[e] + A64 * k4[e] + A65 * k5[e]);
        __syncthreads();
        vf(yts, k6, w1p, b1s, w2p, b2s, b3s, dxs, h1, h2, tid);

        // y update
#pragma unroll
        for (int e = tid; e < 512; e += NT)
            ybuf[e] = ybuf[e] + dt * (B1 * k1[e] + B2 * k2[e] + B3 * k3[e]
                                    + B4 * k4[e] + B5 * k5[e] + B6 * k6[e]);
        __syncthreads();
        write_out(ybuf, lws, lbv, out, b0, t + 1, tid);
        __syncthreads();
    }
}

extern "C" void kernel_launch(void* const* d_in, const int* in_sizes, int n_in,
                              void* d_out, int out_size) {
    const float* ts  = (const float*)d_in[0];
    const float* xs  = (const float*)d_in[1];
    const float* iw1 = (const float*)d_in[2];
    const float* ib1 = (const float*)d_in[3];
    const float* iw2 = (const float*)d_in[4];
    const float* ib2 = (const float*)d_in[5];
    const float* iw3 = (const float*)d_in[6];
    const float* ib3 = (const float*)d_in[7];
    const float* vw1 = (const float*)d_in[8];
    const float* vb1 = (const float*)d_in[9];
    const float* vw2 = (const float*)d_in[10];
    const float* vb2 = (const float*)d_in[11];
    const float* vw3 = (const float*)d_in[12];
    const float* vb3 = (const float*)d_in[13];
    const float* lw  = (const float*)d_in[14];
    const float* lb  = (const float*)d_in[15];
    float* out = (float*)d_out;

    prep_vw3<<<256, 256>>>(vw3);

    cudaFuncSetAttribute(cde_kernel, cudaFuncAttributeMaxDynamicSharedMemorySize, SMEM_BYTES);
    cde_kernel<<<128, NT, SMEM_BYTES>>>(ts, xs, iw1, ib1, iw2, ib2, iw3, ib3,
                                        vw1, vb1, vw2, vb2, vb3, lw, lb, out);
}

// round 6
// speedup vs baseline: 1.0938x; 1.0938x over previous
#include <cuda_runtime.h>

#define NT 512
#define BT 8

typedef unsigned long long u64;

// ---------------- packed f32x2 helpers ----------------
__device__ __forceinline__ void ffma2(u64 &acc, u64 a, u64 w) {
    asm("fma.rn.f32x2 %0, %1, %2, %0;" : "+l"(acc) : "l"(a), "l"(w));
}
__device__ __forceinline__ float sum2(u64 v) {
    return __uint_as_float((unsigned int)v) + __uint_as_float((unsigned int)(v >> 32));
}

// ---------------- activations ----------------
__device__ __forceinline__ float softplus_f(float x) {
    float r = __logf(1.f + __expf(x));
    return (x > 15.f) ? x : r;
}
__device__ __forceinline__ float tanh_f(float x) {
    float xx = fminf(fmaxf(x, -12.f), 12.f);
    float e = __expf(2.f * xx);
    return (e - 1.f) * __fdividef(1.f, e + 1.f);
}

// ---------------- k-major quad-interleaved weight layouts ----------------
// dst[(k>>2)*C*4 + c*4 + (k&3)] = src[c*K + k]
__device__ float g_vw3q[512 * 128];
__device__ float g_vw1k[128 * 64];
__device__ float g_vw2k[128 * 128];
__device__ float g_iw1k[128 * 8];
__device__ float g_iw2k[128 * 128];
__device__ float g_iw3k[64 * 128];

__global__ void prep_kmajor(float* __restrict__ dst, const float* __restrict__ src,
                            int C, int K) {
    int id = blockIdx.x * blockDim.x + threadIdx.x;
    if (id >= C * K) return;
    int c = id / K;
    int k = id % K;
    dst[(k >> 2) * C * 4 + c * 4 + (k & 3)] = src[id];
}

// ---------------- smem layout (floats) ----------------
#define OFF_W1 0          // vw1 k-major: 16 kq x 128 x 4 = 8192
#define OFF_W2 8192       // vw2 k-major: 32 kq x 128 x 4 = 16384
#define OFF_B1 24576      // 128
#define OFF_B2 24704      // 128
#define OFF_B3 24832      // 512
#define OFF_LW 25344      // 64
#define OFF_Y  25408      // 8 x 64
#define OFF_YT 25920      // 8 x 64
#define OFF_H1 26432      // 8 x 128
#define OFF_H2 27456      // 8 x 128
#define OFF_K  28480      // 6 x 512
#define OFF_DX 31552      // 8 x 8
#define OFF_SC 31616      // scratch: 2 x 4096 (l3 partials; dense partials reuse)
#define SMEM_FLOATS (31616 + 8192)
#define SMEM_BYTES (SMEM_FLOATS * 4)

enum { ACT_ID = 0, ACT_RELU = 1, ACT_SP = 2 };

// Split-K dense: OUT[8][C] = act( ACTS[8][K] @ W^T + bias ).
// Threads 0-255 accumulate k-half 0, threads 256-511 k-half 1; partials meet
// in scratch, reduced by all 512 threads. Weights are k-major quad-interleaved
// (LDS.128 contiguous across the warp; conflict-free). Acts are warp-broadcast.
// Caller must __syncthreads() after return before reading outp or reusing scratch.
template<int C, int K, int ACT>
__device__ __forceinline__ void dense_sk(const float* __restrict__ wk,
                                         const float* __restrict__ bias,
                                         const float* __restrict__ actbuf,
                                         float* __restrict__ scratch,
                                         float* __restrict__ outp, int tid) {
    const int half = tid >> 8;
    const int t2 = tid & 255;
    constexpr int G = 256 / C;          // row groups per half
    constexpr int RPT = 8 / G;          // rows per thread
    constexpr int KQH = K / 8;          // k-quads per half
    const int c  = t2 % C;
    const int r0 = (t2 / C) * RPT;
    const int kq0 = half * KQH;

    u64 acc[RPT][2];
#pragma unroll
    for (int i = 0; i < RPT; i++) { acc[i][0] = 0ull; acc[i][1] = 0ull; }

#pragma unroll
    for (int q = 0; q < KQH; q++) {
        const int kq = kq0 + q;
        ulonglong2 w = *(const ulonglong2*)(wk + kq * C * 4 + c * 4);
#pragma unroll
        for (int i = 0; i < RPT; i++) {
            ulonglong2 a = *(const ulonglong2*)(actbuf + (r0 + i) * K + kq * 4);
            ffma2(acc[i][0], a.x, w.x);
            ffma2(acc[i][1], a.y, w.y);
        }
    }
#pragma unroll
    for (int i = 0; i < RPT; i++)
        scratch[half * (8 * C) + (r0 + i) * C + c] = sum2(acc[i][0]) + sum2(acc[i][1]);
    __syncthreads();

#pragma unroll
    for (int i = tid; i < 8 * C; i += NT) {
        float v = scratch[i] + scratch[8 * C + i] + bias[i % C];
        if (ACT == ACT_RELU) v = fmaxf(v, 0.f);
        if (ACT == ACT_SP)   v = softplus_f(v);
        outp[i] = v;
    }
}

// L3 (512 cols, K=128) split-K + tanh + dx-contraction -> kout[8][64].
// Each half: thread t2 owns cols t2 and t2+256 for all 8 rows over 64 k.
__device__ __forceinline__ void l3_sk(const float* __restrict__ h2s,
                                      const float* __restrict__ b3s,
                                      const float* __restrict__ dxs,
                                      float* __restrict__ scratch,
                                      float* __restrict__ kout, int tid) {
    const int half = tid >> 8;
    const int t2 = tid & 255;

    u64 acc0[8], acc1[8];
#pragma unroll
    for (int r = 0; r < 8; r++) { acc0[r] = 0ull; acc1[r] = 0ull; }

    const float* gb = g_vw3q + (half * 16) * 2048 + t2 * 4;
    // depth-2 register prefetch on the streamed weights
    ulonglong2 p00 = *(const ulonglong2*)(gb);
    ulonglong2 p01 = *(const ulonglong2*)(gb + 1024);
    ulonglong2 p10 = *(const ulonglong2*)(gb + 2048);
    ulonglong2 p11 = *(const ulonglong2*)(gb + 2048 + 1024);

#pragma unroll
    for (int q = 0; q < 16; q++) {
        ulonglong2 w0 = p00, w1 = p01;
        p00 = p10; p01 = p11;
        if (q + 2 < 16) {
            p10 = *(const ulonglong2*)(gb + (q + 2) * 2048);
            p11 = *(const ulonglong2*)(gb + (q + 2) * 2048 + 1024);
        }
        const int k4 = (half * 16 + q) * 4;
#pragma unroll
        for (int r = 0; r < 8; r++) {
            ulonglong2 a = *(const ulonglong2*)(h2s + r * 128 + k4);
            ffma2(acc0[r], a.x, w0.x);
            ffma2(acc0[r], a.y, w0.y);
            ffma2(acc1[r], a.x, w1.x);
            ffma2(acc1[r], a.y, w1.y);
        }
    }
#pragma unroll
    for (int r = 0; r < 8; r++) {
        scratch[half * 4096 + r * 512 + t2]       = sum2(acc0[r]);
        scratch[half * 4096 + r * 512 + t2 + 256] = sum2(acc1[r]);
    }
    __syncthreads();

    // contract: thread = col c = tid (512 cols), all 8 rows; shuffle over d
    const int d  = tid & 7;
    const int h0 = tid >> 3;
    const float b3v = b3s[tid];
#pragma unroll
    for (int r = 0; r < 8; r++) {
        float v = scratch[r * 512 + tid] + scratch[4096 + r * 512 + tid] + b3v;
        float f = tanh_f(v) * dxs[r * 8 + d];
        f += __shfl_xor_sync(0xffffffffu, f, 1);
        f += __shfl_xor_sync(0xffffffffu, f, 2);
        f += __shfl_xor_sync(0xffffffffu, f, 4);
        if (d == 0) kout[r * 64 + h0] = f;
    }
}

__device__ __forceinline__ void vf(const float* __restrict__ ysrc, float* __restrict__ kout,
                                   const float* w1k, const float* b1s,
                                   const float* w2k, const float* b2s,
                                   const float* b3s, const float* dxs,
                                   float* scratch, float* h1, float* h2, int tid) {
    dense_sk<128, 64, ACT_SP>(w1k, b1s, ysrc, scratch, h1, tid);
    __syncthreads();
    dense_sk<128, 128, ACT_SP>(w2k, b2s, h1, scratch, h2, tid);
    __syncthreads();
    l3_sk(h2, b3s, dxs, scratch, kout, tid);
    __syncthreads();
}

__device__ __forceinline__ void write_out(const float* __restrict__ y,
                                          const float* __restrict__ lws, float lbv,
                                          float* __restrict__ out, int b0, int t, int tid) {
    int w = tid >> 5, l = tid & 31;
    if (w < 8) {
        float p = y[w * 64 + l] * lws[l] + y[w * 64 + 32 + l] * lws[32 + l];
#pragma unroll
        for (int s = 16; s > 0; s >>= 1) p += __shfl_xor_sync(0xffffffffu, p, s);
        if (l == 0) {
            float z = p + lbv;
            out[(b0 + w) * 64 + t] = __fdividef(1.f, 1.f + __expf(-z));
        }
    }
}

__global__ void __launch_bounds__(NT, 1)
cde_kernel(const float* __restrict__ ts, const float* __restrict__ xs,
           const float* __restrict__ ib1, const float* __restrict__ ib2,
           const float* __restrict__ ib3,
           const float* __restrict__ vb1, const float* __restrict__ vb2,
           const float* __restrict__ vb3,
           const float* __restrict__ lw, const float* __restrict__ lb,
           float* __restrict__ out) {
    extern __shared__ float sm[];
    const int tid = threadIdx.x;
    const int b0 = blockIdx.x * BT;

    float* w1k = sm + OFF_W1;
    float* w2k = sm + OFF_W2;
    float* b1s = sm + OFF_B1;
    float* b2s = sm + OFF_B2;
    float* b3s = sm + OFF_B3;
    float* lws = sm + OFF_LW;
    float* ybuf = sm + OFF_Y;
    float* yts = sm + OFF_YT;
    float* h1 = sm + OFF_H1;
    float* h2 = sm + OFF_H2;
    float* ksb = sm + OFF_K;
    float* dxs = sm + OFF_DX;
    float* scratch = sm + OFF_SC;

    // ---------- stage weights + misc into smem ----------
    for (int i = tid; i < 128 * 64; i += NT)  w1k[i] = g_vw1k[i];
    for (int i = tid; i < 128 * 128; i += NT) w2k[i] = g_vw2k[i];
    for (int i = tid; i < 128; i += NT) { b1s[i] = vb1[i]; b2s[i] = vb2[i]; }
    for (int i = tid; i < 512; i += NT) b3s[i] = vb3[i];
    if (tid < 64) lws[tid] = lw[tid];
    if (tid < 64) {
        int r = tid >> 3, d = tid & 7;
        dxs[tid] = xs[(b0 + r) * 512 + d];         // X(t0)
    }
    const float lbv = lb[0];
    __syncthreads();

    // ---------- initial MLP (weights straight from global k-major) ----------
    dense_sk<128, 8, ACT_RELU>(g_iw1k, ib1, dxs, scratch, h1, tid);
    __syncthreads();
    dense_sk<128, 128, ACT_RELU>(g_iw2k, ib2, h1, scratch, h2, tid);
    __syncthreads();
    dense_sk<64, 128, ACT_ID>(g_iw3k, ib3, h2, scratch, ybuf, tid);
    __syncthreads();

    write_out(ybuf, lws, lbv, out, b0, 0, tid);
    __syncthreads();

    // Tsit5 coefficients
    const float A21 = 0.161f;
    const float A31 = -0.008480655492356989f, A32 = 0.335480655492357f;
    const float A41 = 2.8971530571054935f, A42 = -6.359448489975075f, A43 = 4.3622954328695815f;
    const float A51 = 5.325864828439257f, A52 = -11.748883564062828f, A53 = 7.4955393428898365f, A54 = -0.09249506636175525f;
    const float A61 = 5.86145544294642f, A62 = -12.92096931784711f, A63 = 8.159367898576159f, A64 = -0.071584973281401f, A65 = -0.028269050394068383f;
    const float B1 = 0.09646076681806523f, B2 = 0.01f, B3 = 0.4798896504144996f;
    const float B4 = 1.379008574103742f, B5 = -3.290069515436081f, B6 = 2.324710524099774f;

    float* k1 = ksb;
    float* k2 = ksb + 512;
    float* k3 = ksb + 1024;
    float* k4 = ksb + 1536;
    float* k5 = ksb + 2048;
    float* k6 = ksb + 2560;

    for (int t = 0; t < 63; t++) {
        const float dt = ts[t + 1] - ts[t];
        if (tid < 64) {
            int r = tid >> 3, d = tid & 7;
            int ix = (b0 + r) * 512 + t * 8 + d;
            dxs[tid] = (xs[ix + 8] - xs[ix]) / dt;
        }
        __syncthreads();

        // stage 1
        vf(ybuf, k1, w1k, b1s, w2k, b2s, b3s, dxs, scratch, h1, h2, tid);
        // stage 2
        {
            int e = tid;
            yts[e] = ybuf[e] + dt * (A21 * k1[e]);
        }
        __syncthreads();
        vf(yts, k2, w1k, b1s, w2k, b2s, b3s, dxs, scratch, h1, h2, tid);
        // stage 3
        {
            int e = tid;
            yts[e] = ybuf[e] + dt * (A31 * k1[e] + A32 * k2[e]);
        }
        __syncthreads();
        vf(yts, k3, w1k, b1s, w2k, b2s, b3s, dxs, scratch, h1, h2, tid);
        // stage 4
        {
            int e = tid;
            yts[e] = ybuf[e] + dt * (A41 * k1[e] + A42 * k2[e] + A43 * k3[e]);
        }
        __syncthreads();
        vf(yts, k4, w1k, b1s, w2k, b2s, b3s, dxs, scratch, h1, h2, tid);
        // stage 5
        {
            int e = tid;
            yts[e] = ybuf[e] + dt * (A51 * k1[e] + A52 * k2[e] + A53 * k3[e] + A54 * k4[e]);
        }
        __syncthreads();
        vf(yts, k5, w1k, b1s, w2k, b2s, b3s, dxs, scratch, h1, h2, tid);
        // stage 6
        {
            int e = tid;
            yts[e] = ybuf[e] + dt * (A61 * k1[e] + A62 * k2[e] + A63 * k3[e] + A64 * k4[e] + A65 * k5[e]);
        }
        __syncthreads();
        vf(yts, k6, w1k, b1s, w2k, b2s, b3s, dxs, scratch, h1, h2, tid);

        // y update
        {
            int e = tid;
            ybuf[e] = ybuf[e] + dt * (B1 * k1[e] + B2 * k2[e] + B3 * k3[e]
                                    + B4 * k4[e] + B5 * k5[e] + B6 * k6[e]);
        }
        __syncthreads();
        write_out(ybuf, lws, lbv, out, b0, t + 1, tid);
        __syncthreads();
    }
}

extern "C" void kernel_launch(void* const* d_in, const int* in_sizes, int n_in,
                              void* d_out, int out_size) {
    const float* ts  = (const float*)d_in[0];
    const float* xs  = (const float*)d_in[1];
    const float* iw1 = (const float*)d_in[2];
    const float* ib1 = (const float*)d_in[3];
    const float* iw2 = (const float*)d_in[4];
    const float* ib2 = (const float*)d_in[5];
    const float* iw3 = (const float*)d_in[6];
    const float* ib3 = (const float*)d_in[7];
    const float* vw1 = (const float*)d_in[8];
    const float* vb1 = (const float*)d_in[9];
    const float* vw2 = (const float*)d_in[10];
    const float* vb2 = (const float*)d_in[11];
    const float* vw3 = (const float*)d_in[12];
    const float* vb3 = (const float*)d_in[13];
    const float* lw  = (const float*)d_in[14];
    const float* lb  = (const float*)d_in[15];
    float* out = (float*)d_out;

    float *p_vw3q, *p_vw1k, *p_vw2k, *p_iw1k, *p_iw2k, *p_iw3k;
    cudaGetSymbolAddress((void**)&p_vw3q, g_vw3q);
    cudaGetSymbolAddress((void**)&p_vw1k, g_vw1k);
    cudaGetSymbolAddress((void**)&p_vw2k, g_vw2k);
    cudaGetSymbolAddress((void**)&p_iw1k, g_iw1k);
    cudaGetSymbolAddress((void**)&p_iw2k, g_iw2k);
    cudaGetSymbolAddress((void**)&p_iw3k, g_iw3k);

    prep_kmajor<<<(512 * 128 + 255) / 256, 256>>>(p_vw3q, vw3, 512, 128);
    prep_kmajor<<<(128 * 64 + 255) / 256, 256>>>(p_vw1k, vw1, 128, 64);
    prep_kmajor<<<(128 * 128 + 255) / 256, 256>>>(p_vw2k, vw2, 128, 128);
    prep_kmajor<<<(128 * 8 + 255) / 256, 256>>>(p_iw1k, iw1, 128, 8);
    prep_kmajor<<<(128 * 128 + 255) / 256, 256>>>(p_iw2k, iw2, 128, 128);
    prep_kmajor<<<(64 * 128 + 255) / 256, 256>>>(p_iw3k, iw3, 64, 128);

    cudaFuncSetAttribute(cde_kernel, cudaFuncAttributeMaxDynamicSharedMemorySize, SMEM_BYTES);
    cde_kernel<<<128, NT, SMEM_BYTES>>>(ts, xs, ib1, ib2, ib3,
                                        vb1, vb2, vb3, lw, lb, out);
}